// round 1
// baseline (speedup 1.0000x reference)
#include <cuda_runtime.h>
#include <cstdint>
#include <cstdio>

#define NUM_B 16
#define SEQ_N 1025
#define NHEAD 12
#define HDIM  64
#define DMODEL 768
#define M_ROWS (NUM_B * SEQ_N)   // 16400

// ---------------- scratch (no allocations allowed) ----------------
__device__ float g_Q[NUM_B * NHEAD * SEQ_N * HDIM];
__device__ float g_K[NUM_B * NHEAD * SEQ_N * HDIM];
__device__ float g_V[NUM_B * NHEAD * SEQ_N * HDIM];
__device__ float g_ctx[NUM_B * SEQ_N * DMODEL];

// =================================================================
// TN GEMM: C[m, d] = sum_k A[m,k] * B[d,k]
// Tile 128x64x16, 256 threads, 8x4 micro-tile.
// MODE 0: A = x, B = W_qkv -> epilogue applies RoPE, scatters to g_Q/g_K/g_V
// MODE 1: A = g_ctx, B = W_proj -> epilogue adds bias, writes to out
// =================================================================
template<int MODE>
__global__ __launch_bounds__(256) void gemm_tn(
    const float* __restrict__ A, const float* __restrict__ Bm,
    int M, int K,
    float* __restrict__ out, const float* __restrict__ bias,
    const float* __restrict__ freqs)
{
    __shared__ float As[16][132];   // [k][m], padded
    __shared__ float Bs[16][68];    // [k][n], padded

    const int tid = threadIdx.x;
    const int tx = tid & 15;
    const int ty = tid >> 4;
    const int m0 = blockIdx.x * 128;
    const int n0 = blockIdx.y * 64;

    const float* Ap = (MODE == 1) ? g_ctx : A;

    float acc[8][4];
#pragma unroll
    for (int i = 0; i < 8; i++)
#pragma unroll
        for (int j = 0; j < 4; j++) acc[i][j] = 0.f;

    const int ar0 = tid >> 2;          // 0..63 (and +64)
    const int ac0 = (tid & 3) * 4;     // 0,4,8,12
    const int br  = tid >> 2;
    const int bc0 = (tid & 3) * 4;

    for (int k0 = 0; k0 < K; k0 += 16) {
        // load A tile (2 float4 per thread), guard rows
#pragma unroll
        for (int half = 0; half < 2; half++) {
            int row = ar0 + half * 64;
            int gm = m0 + row;
            float4 v = make_float4(0.f, 0.f, 0.f, 0.f);
            if (gm < M) v = *(const float4*)&Ap[(size_t)gm * K + k0 + ac0];
            As[ac0 + 0][row] = v.x;
            As[ac0 + 1][row] = v.y;
            As[ac0 + 2][row] = v.z;
            As[ac0 + 3][row] = v.w;
        }
        {
            int gn = n0 + br;   // Nc always divisible by 64
            float4 v = *(const float4*)&Bm[(size_t)gn * K + k0 + bc0];
            Bs[bc0 + 0][br] = v.x;
            Bs[bc0 + 1][br] = v.y;
            Bs[bc0 + 2][br] = v.z;
            Bs[bc0 + 3][br] = v.w;
        }
        __syncthreads();

#pragma unroll
        for (int kk = 0; kk < 16; kk++) {
            float4 a0 = *(const float4*)&As[kk][ty * 8];
            float4 a1 = *(const float4*)&As[kk][ty * 8 + 4];
            float4 b  = *(const float4*)&Bs[kk][tx * 4];
            float a[8] = {a0.x, a0.y, a0.z, a0.w, a1.x, a1.y, a1.z, a1.w};
            float bb[4] = {b.x, b.y, b.z, b.w};
#pragma unroll
            for (int i = 0; i < 8; i++)
#pragma unroll
                for (int j = 0; j < 4; j++)
                    acc[i][j] = fmaf(a[i], bb[j], acc[i][j]);
        }
        __syncthreads();
    }

    const int col0 = n0 + tx * 4;

    if (MODE == 0) {
        // col0 -> (s, h, e0): s in {0,1,2}, e0 multiple of 4
        const int sidx = col0 / DMODEL;
        const int rcol = col0 - sidx * DMODEL;
        const int h  = rcol >> 6;
        const int e0 = rcol & 63;
        float* dst = (sidx == 0) ? g_Q : (sidx == 1) ? g_K : g_V;

        float f0a = 0.f, f1a = 0.f, f0b = 0.f, f1b = 0.f;
        if (sidx < 2) {
            int jj0 = (e0 >> 1) + h * 32;
            f0a = freqs[jj0];
            f1a = freqs[384 + jj0];
            f0b = freqs[jj0 + 1];
            f1b = freqs[384 + jj0 + 1];
        }
#pragma unroll
        for (int i = 0; i < 8; i++) {
            int gm = m0 + ty * 8 + i;
            if (gm >= M) break;
            int b = gm / SEQ_N;
            int n = gm - b * SEQ_N;
            float v0 = acc[i][0], v1 = acc[i][1], v2 = acc[i][2], v3 = acc[i][3];
            if (sidx < 2 && n >= 1) {
                int t = n - 1;
                float txc = (float)(t & 31);
                float tyc = (float)(t >> 5);
                float ang0 = txc * f0a + tyc * f1a;
                float ang1 = txc * f0b + tyc * f1b;
                float s0, c0, s1, c1;
                sincosf(ang0, &s0, &c0);
                sincosf(ang1, &s1, &c1);
                float a0 = v0, b0 = v1;
                v0 = a0 * c0 - b0 * s0;
                v1 = a0 * s0 + b0 * c0;
                float a1 = v2, b1 = v3;
                v2 = a1 * c1 - b1 * s1;
                v3 = a1 * s1 + b1 * c1;
            }
            size_t off = ((size_t)((b * NHEAD + h) * SEQ_N + n)) * HDIM + e0;
            *(float4*)&dst[off] = make_float4(v0, v1, v2, v3);
        }
    } else {
        float4 bv = *(const float4*)&bias[col0];
#pragma unroll
        for (int i = 0; i < 8; i++) {
            int gm = m0 + ty * 8 + i;
            if (gm >= M) break;
            *(float4*)&out[(size_t)gm * DMODEL + col0] =
                make_float4(acc[i][0] + bv.x, acc[i][1] + bv.y,
                            acc[i][2] + bv.z, acc[i][3] + bv.w);
        }
    }
}

// =================================================================
// Flash attention, fp32. One block per (b*h, 64-query tile).
// 256 threads (16x16), 4x4 micro-tiles, KV tiles of 64, online softmax.
// Dynamic smem: Qs[64][65] Ps[64][65] Kt[64][68] Vs[64][68] = 68096 B
// =================================================================
#define ATTN_SMEM_BYTES ((64 * 65 * 2 + 64 * 68 * 2) * 4)

__device__ __forceinline__ float redmax16(float v) {
#pragma unroll
    for (int o = 8; o; o >>= 1)
        v = fmaxf(v, __shfl_xor_sync(0xffffffffu, v, o));
    return v;
}
__device__ __forceinline__ float redsum16(float v) {
#pragma unroll
    for (int o = 8; o; o >>= 1)
        v += __shfl_xor_sync(0xffffffffu, v, o);
    return v;
}

__global__ __launch_bounds__(256) void attn_kernel()
{
    extern __shared__ float sm[];
    float* Qs = sm;                 // [64][65]
    float* Ps = Qs + 64 * 65;       // [64][65]
    float* Kt = Ps + 64 * 65;       // [64][68]  (e-major: Kt[e][n])
    float* Vs = Kt + 64 * 68;       // [64][68]  (n-major)

    const int tid = threadIdx.x;
    const int tx = tid & 15;
    const int ty = tid >> 4;
    const int q0 = blockIdx.x * 64;
    const int bh = blockIdx.y;                  // b*12 + h
    const size_t base = (size_t)bh * SEQ_N * HDIM;

    // load Q tile (natural layout, pad 65)
#pragma unroll
    for (int it = 0; it < 4; it++) {
        int f = tid + it * 256;
        int row = f >> 4;
        int c0 = (f & 15) * 4;
        float4 v = make_float4(0.f, 0.f, 0.f, 0.f);
        if (q0 + row < SEQ_N)
            v = *(const float4*)&g_Q[base + (size_t)(q0 + row) * HDIM + c0];
        Qs[row * 65 + c0 + 0] = v.x;
        Qs[row * 65 + c0 + 1] = v.y;
        Qs[row * 65 + c0 + 2] = v.z;
        Qs[row * 65 + c0 + 3] = v.w;
    }

    float m_i[4], l_i[4], o[4][4];
#pragma unroll
    for (int i = 0; i < 4; i++) {
        m_i[i] = -1e30f;
        l_i[i] = 0.f;
#pragma unroll
        for (int j = 0; j < 4; j++) o[i][j] = 0.f;
    }

    for (int kt = 0; kt < 17; kt++) {
        const int kv0 = kt * 64;
        __syncthreads();   // prior PV reads done before overwriting K/V
        // load K -> Kt (transposed), V -> Vs (natural)
#pragma unroll
        for (int it = 0; it < 4; it++) {
            int f = tid + it * 256;
            int row = f >> 4;
            int c0 = (f & 15) * 4;
            int gk = kv0 + row;
            float4 kv = make_float4(0.f, 0.f, 0.f, 0.f);
            float4 vv = make_float4(0.f, 0.f, 0.f, 0.f);
            if (gk < SEQ_N) {
                size_t off = base + (size_t)gk * HDIM + c0;
                kv = *(const float4*)&g_K[off];
                vv = *(const float4*)&g_V[off];
            }
            Kt[(c0 + 0) * 68 + row] = kv.x;
            Kt[(c0 + 1) * 68 + row] = kv.y;
            Kt[(c0 + 2) * 68 + row] = kv.z;
            Kt[(c0 + 3) * 68 + row] = kv.w;
            *(float4*)&Vs[row * 68 + c0] = vv;
        }
        __syncthreads();

        // S = Q K^T  (4x4 per thread)
        float s[4][4];
#pragma unroll
        for (int i = 0; i < 4; i++)
#pragma unroll
            for (int j = 0; j < 4; j++) s[i][j] = 0.f;

#pragma unroll 16
        for (int k = 0; k < 64; k++) {
            float qr[4];
#pragma unroll
            for (int i = 0; i < 4; i++) qr[i] = Qs[(ty * 4 + i) * 65 + k];
            float4 kk4 = *(const float4*)&Kt[k * 68 + tx * 4];
            float kb[4] = {kk4.x, kk4.y, kk4.z, kk4.w};
#pragma unroll
            for (int i = 0; i < 4; i++)
#pragma unroll
                for (int j = 0; j < 4; j++)
                    s[i][j] = fmaf(qr[i], kb[j], s[i][j]);
        }

        // scale + mask oob kv columns
#pragma unroll
        for (int i = 0; i < 4; i++)
#pragma unroll
            for (int j = 0; j < 4; j++) {
                float v = s[i][j] * 0.125f;
                if (kv0 + tx * 4 + j >= SEQ_N) v = -1e30f;
                s[i][j] = v;
            }

        // online softmax update
#pragma unroll
        for (int i = 0; i < 4; i++) {
            float mx = fmaxf(fmaxf(s[i][0], s[i][1]), fmaxf(s[i][2], s[i][3]));
            mx = redmax16(mx);
            float mnew = fmaxf(m_i[i], mx);
            float c = __expf(m_i[i] - mnew);
            float sum = 0.f;
#pragma unroll
            for (int j = 0; j < 4; j++) {
                float p = __expf(s[i][j] - mnew);
                s[i][j] = p;
                sum += p;
            }
            sum = redsum16(sum);
            l_i[i] = l_i[i] * c + sum;
            m_i[i] = mnew;
#pragma unroll
            for (int j = 0; j < 4; j++) o[i][j] *= c;
        }

        // write P tile
#pragma unroll
        for (int i = 0; i < 4; i++)
#pragma unroll
            for (int j = 0; j < 4; j++)
                Ps[(ty * 4 + i) * 65 + tx * 4 + j] = s[i][j];
        __syncthreads();

        // O += P V
#pragma unroll 16
        for (int k = 0; k < 64; k++) {
            float pr[4];
#pragma unroll
            for (int i = 0; i < 4; i++) pr[i] = Ps[(ty * 4 + i) * 65 + k];
            float4 vv = *(const float4*)&Vs[k * 68 + tx * 4];
            float vb[4] = {vv.x, vv.y, vv.z, vv.w};
#pragma unroll
            for (int i = 0; i < 4; i++)
#pragma unroll
                for (int j = 0; j < 4; j++)
                    o[i][j] = fmaf(pr[i], vb[j], o[i][j]);
        }
    }

    // write context: ctx[b, q, h*64 + e]
    const int h = bh % NHEAD;
    const int b = bh / NHEAD;
#pragma unroll
    for (int i = 0; i < 4; i++) {
        int q = q0 + ty * 4 + i;
        if (q < SEQ_N) {
            float inv = 1.0f / l_i[i];
            size_t off = ((size_t)(b * SEQ_N + q)) * DMODEL + h * HDIM + tx * 4;
            *(float4*)&g_ctx[off] = make_float4(o[i][0] * inv, o[i][1] * inv,
                                                o[i][2] * inv, o[i][3] * inv);
        }
    }
}

// =================================================================
extern "C" void kernel_launch(void* const* d_in, const int* in_sizes, int n_in,
                              void* d_out, int out_size)
{
    const float* x     = (const float*)d_in[0];
    const float* Wqkv  = (const float*)d_in[1];
    const float* Wproj = (const float*)d_in[2];
    const float* bproj = (const float*)d_in[3];
    const float* freqs = (const float*)d_in[4];
    float* out = (float*)d_out;

    // 1) QKV GEMM + fused RoPE -> g_Q/g_K/g_V
    {
        dim3 grid((M_ROWS + 127) / 128, (3 * DMODEL) / 64);
        gemm_tn<0><<<grid, 256>>>(x, Wqkv, M_ROWS, DMODEL, nullptr, nullptr, freqs);
    }

    // 2) attention -> g_ctx
    {
        cudaFuncSetAttribute(attn_kernel,
                             cudaFuncAttributeMaxDynamicSharedMemorySize,
                             ATTN_SMEM_BYTES);
        dim3 grid((SEQ_N + 63) / 64, NUM_B * NHEAD);
        attn_kernel<<<grid, 256, ATTN_SMEM_BYTES>>>();
    }

    // 3) proj GEMM + bias -> out
    {
        dim3 grid((M_ROWS + 127) / 128, DMODEL / 64);
        gemm_tn<1><<<grid, 256>>>(nullptr, Wproj, M_ROWS, DMODEL, out, bproj, nullptr);
    }
}

// round 2
// speedup vs baseline: 2.6628x; 2.6628x over previous
#include <cuda_runtime.h>
#include <cstdint>

#define NUM_B 16
#define SEQ_N 1025
#define NHEAD 12
#define HDIM  64
#define DMODEL 768
#define M_ROWS (NUM_B * SEQ_N)   // 16400

// ---------------- scratch (no allocations allowed) ----------------
__device__ float g_Q[NUM_B * NHEAD * SEQ_N * HDIM];
__device__ float g_K[NUM_B * NHEAD * SEQ_N * HDIM];
__device__ float g_V[NUM_B * NHEAD * SEQ_N * HDIM];
__device__ float g_ctx[NUM_B * SEQ_N * DMODEL];

// ---------------- tf32 helpers ----------------
__device__ __forceinline__ uint32_t f2tf(float f) {
    uint32_t r;
    asm("cvt.rna.tf32.f32 %0, %1;" : "=r"(r) : "f"(f));
    return r;
}

// D = A(16x8) * B(8x8) + D, tf32 inputs, fp32 accum
__device__ __forceinline__ void mma8(float* c, const uint32_t* a, const uint32_t* b) {
    asm volatile(
        "mma.sync.aligned.m16n8k8.row.col.f32.tf32.tf32.f32 "
        "{%0,%1,%2,%3}, {%4,%5,%6,%7}, {%8,%9}, {%0,%1,%2,%3};\n"
        : "+f"(c[0]), "+f"(c[1]), "+f"(c[2]), "+f"(c[3])
        : "r"(a[0]), "r"(a[1]), "r"(a[2]), "r"(a[3]), "r"(b[0]), "r"(b[1]));
}

// =================================================================
// TN GEMM via tf32 tensor cores: C[m,d] = sum_k A[m,k]*B[d,k]
// Block 128x64, 8 warps of 32x32, k-step 32.
// MODE 0: epilogue RoPE -> g_Q/g_K/g_V.  MODE 1: bias -> out.
// =================================================================
template<int MODE>
__global__ __launch_bounds__(256) void gemm_tc(
    const float* __restrict__ A, const float* __restrict__ Bw,
    float* __restrict__ out, const float* __restrict__ bias,
    const float* __restrict__ freqs)
{
    __shared__ uint32_t As[128][36];   // [m][k] tf32 bits
    __shared__ uint32_t Bs[64][36];    // [n][k] tf32 bits

    const int tid = threadIdx.x;
    const int lane = tid & 31;
    const int wid = tid >> 5;
    const int wm = wid & 3;       // 0..3 -> m group of 32
    const int wn = wid >> 2;      // 0..1 -> n group of 32
    const int m0 = blockIdx.x * 128;
    const int n0 = blockIdx.y * 64;

    const float* Ap = (MODE == 1) ? g_ctx : A;

    float c[2][4][4];
#pragma unroll
    for (int i = 0; i < 2; i++)
#pragma unroll
        for (int j = 0; j < 4; j++)
#pragma unroll
            for (int r = 0; r < 4; r++) c[i][j][r] = 0.f;

    const int ldr = tid >> 3;            // 0..31
    const int ldc = (tid & 7) * 4;       // 0,4,..,28

    for (int k0 = 0; k0 < DMODEL; k0 += 32) {
        // stage A tile (128x32) as tf32
#pragma unroll
        for (int it = 0; it < 4; it++) {
            int m = ldr + it * 32;
            int gm = m0 + m;
            float4 v = make_float4(0.f, 0.f, 0.f, 0.f);
            if (gm < M_ROWS) v = *(const float4*)&Ap[(size_t)gm * DMODEL + k0 + ldc];
            As[m][ldc + 0] = f2tf(v.x);
            As[m][ldc + 1] = f2tf(v.y);
            As[m][ldc + 2] = f2tf(v.z);
            As[m][ldc + 3] = f2tf(v.w);
        }
        // stage B tile (64x32)
#pragma unroll
        for (int it = 0; it < 2; it++) {
            int n = ldr + it * 32;
            float4 v = *(const float4*)&Bw[(size_t)(n0 + n) * DMODEL + k0 + ldc];
            Bs[n][ldc + 0] = f2tf(v.x);
            Bs[n][ldc + 1] = f2tf(v.y);
            Bs[n][ldc + 2] = f2tf(v.z);
            Bs[n][ldc + 3] = f2tf(v.w);
        }
        __syncthreads();

#pragma unroll
        for (int kc = 0; kc < 32; kc += 8) {
            uint32_t a[2][4], b[4][2];
#pragma unroll
            for (int mt = 0; mt < 2; mt++) {
                int mr = wm * 32 + mt * 16 + (lane >> 2);
                a[mt][0] = As[mr][kc + (lane & 3)];
                a[mt][1] = As[mr + 8][kc + (lane & 3)];
                a[mt][2] = As[mr][kc + (lane & 3) + 4];
                a[mt][3] = As[mr + 8][kc + (lane & 3) + 4];
            }
#pragma unroll
            for (int nt = 0; nt < 4; nt++) {
                int nc = wn * 32 + nt * 8 + (lane >> 2);
                b[nt][0] = Bs[nc][kc + (lane & 3)];
                b[nt][1] = Bs[nc][kc + (lane & 3) + 4];
            }
#pragma unroll
            for (int mt = 0; mt < 2; mt++)
#pragma unroll
                for (int nt = 0; nt < 4; nt++)
                    mma8(c[mt][nt], a[mt], b[nt]);
        }
        __syncthreads();
    }

    // -------- epilogue --------
    if (MODE == 0) {
        const int sidx = n0 / DMODEL;            // uniform per block
        const int hh = (n0 % DMODEL) >> 6;       // uniform per block
        float* dst = (sidx == 0) ? g_Q : (sidx == 1) ? g_K : g_V;
#pragma unroll
        for (int nt = 0; nt < 4; nt++) {
            int e0 = wn * 32 + nt * 8 + 2 * (lane & 3);
            float f0 = 0.f, f1 = 0.f;
            if (sidx < 2) {
                int fi = hh * 32 + (e0 >> 1);
                f0 = freqs[fi];
                f1 = freqs[384 + fi];
            }
#pragma unroll
            for (int mt = 0; mt < 2; mt++)
#pragma unroll
                for (int hr = 0; hr < 2; hr++) {
                    int row = m0 + wm * 32 + mt * 16 + (lane >> 2) + hr * 8;
                    if (row >= M_ROWS) continue;
                    int bb = row / SEQ_N;
                    int n = row - bb * SEQ_N;
                    float v0 = c[mt][nt][hr * 2 + 0];
                    float v1 = c[mt][nt][hr * 2 + 1];
                    if (sidx < 2 && n >= 1) {
                        int t = n - 1;
                        float ang = (float)(t & 31) * f0 + (float)(t >> 5) * f1;
                        float sn, cs;
                        sincosf(ang, &sn, &cs);
                        float a0 = v0, b0 = v1;
                        v0 = a0 * cs - b0 * sn;
                        v1 = a0 * sn + b0 * cs;
                    }
                    size_t off = ((size_t)((bb * NHEAD + hh) * SEQ_N + n)) * HDIM + e0;
                    *(float2*)&dst[off] = make_float2(v0, v1);
                }
        }
    } else {
#pragma unroll
        for (int nt = 0; nt < 4; nt++) {
            int col = n0 + wn * 32 + nt * 8 + 2 * (lane & 3);
            float b0v = bias[col], b1v = bias[col + 1];
#pragma unroll
            for (int mt = 0; mt < 2; mt++)
#pragma unroll
                for (int hr = 0; hr < 2; hr++) {
                    int row = m0 + wm * 32 + mt * 16 + (lane >> 2) + hr * 8;
                    if (row >= M_ROWS) continue;
                    *(float2*)&out[(size_t)row * DMODEL + col] =
                        make_float2(c[mt][nt][hr * 2 + 0] + b0v,
                                    c[mt][nt][hr * 2 + 1] + b1v);
                }
        }
    }
}

// =================================================================
// Flash attention with tf32 mma. 128 threads (4 warps).
// Each warp: 16 queries x all keys; kv tiles of 64. Q frags persist
// in registers; P via warp-private smem strip.
// =================================================================
#define ATTN_SMEM_BYTES ((64 * 68 + 64 * 72 + 4 * 16 * 72) * 4)  // 54272

__global__ __launch_bounds__(128) void attn_tc()
{
    extern __shared__ uint32_t dsm[];
    uint32_t* Ks = dsm;                 // [64][68]
    uint32_t* Vs = Ks + 64 * 68;        // [64][72]
    uint32_t* Ps = Vs + 64 * 72;        // [4][16][72]

    const int tid = threadIdx.x;
    const int lane = tid & 31;
    const int w = tid >> 5;
    const int q0 = blockIdx.x * 64;
    const int bh = blockIdx.y;
    const size_t base = (size_t)bh * SEQ_N * HDIM;
    uint32_t* Pw = Ps + w * 16 * 72;

    // ---- stage Q (scaled) into Pw, then register fragments ----
#pragma unroll
    for (int it = 0; it < 8; it++) {
        int slot = lane + it * 32;        // 256 slots: 16 rows x 16 float4
        int r = slot >> 4;
        int cg = (slot & 15) * 4;
        int gq = q0 + w * 16 + r;
        float4 v = make_float4(0.f, 0.f, 0.f, 0.f);
        if (gq < SEQ_N) v = *(const float4*)&g_Q[base + (size_t)gq * HDIM + cg];
        uint4 u;
        u.x = f2tf(v.x * 0.125f);
        u.y = f2tf(v.y * 0.125f);
        u.z = f2tf(v.z * 0.125f);
        u.w = f2tf(v.w * 0.125f);
        *(uint4*)&Pw[r * 72 + cg] = u;
    }
    __syncwarp();
    uint32_t qa[8][4];
#pragma unroll
    for (int kc = 0; kc < 8; kc++) {
        qa[kc][0] = Pw[(lane >> 2) * 72 + kc * 8 + (lane & 3)];
        qa[kc][1] = Pw[((lane >> 2) + 8) * 72 + kc * 8 + (lane & 3)];
        qa[kc][2] = Pw[(lane >> 2) * 72 + kc * 8 + (lane & 3) + 4];
        qa[kc][3] = Pw[((lane >> 2) + 8) * 72 + kc * 8 + (lane & 3) + 4];
    }

    float of[8][4];
#pragma unroll
    for (int i = 0; i < 8; i++)
#pragma unroll
        for (int j = 0; j < 4; j++) of[i][j] = 0.f;
    float m0r = -1e30f, m1r = -1e30f, l0 = 0.f, l1 = 0.f;

    for (int kt = 0; kt < 17; kt++) {
        const int kv0 = kt * 64;
        __syncthreads();
        // stage K,V tiles (64x64) as tf32
#pragma unroll
        for (int it = 0; it < 8; it++) {
            int slot = tid + it * 128;
            int r = slot >> 4;
            int cg = (slot & 15) * 4;
            int gk = kv0 + r;
            float4 kv = make_float4(0.f, 0.f, 0.f, 0.f);
            float4 vv = make_float4(0.f, 0.f, 0.f, 0.f);
            if (gk < SEQ_N) {
                size_t off = base + (size_t)gk * HDIM + cg;
                kv = *(const float4*)&g_K[off];
                vv = *(const float4*)&g_V[off];
            }
            uint4 uk, uv;
            uk.x = f2tf(kv.x); uk.y = f2tf(kv.y); uk.z = f2tf(kv.z); uk.w = f2tf(kv.w);
            uv.x = f2tf(vv.x); uv.y = f2tf(vv.y); uv.z = f2tf(vv.z); uv.w = f2tf(vv.w);
            *(uint4*)&Ks[r * 68 + cg] = uk;
            *(uint4*)&Vs[r * 72 + cg] = uv;
        }
        __syncthreads();

        // ---- S = Q K^T ----
        float s[8][4];
#pragma unroll
        for (int i = 0; i < 8; i++)
#pragma unroll
            for (int j = 0; j < 4; j++) s[i][j] = 0.f;
#pragma unroll
        for (int kc = 0; kc < 8; kc++) {
#pragma unroll
            for (int nt = 0; nt < 8; nt++) {
                uint32_t b[2];
                int key = nt * 8 + (lane >> 2);
                b[0] = Ks[key * 68 + kc * 8 + (lane & 3)];
                b[1] = Ks[key * 68 + kc * 8 + (lane & 3) + 4];
                mma8(s[nt], qa[kc], b);
            }
        }

        if (kt == 16) {
#pragma unroll
            for (int nt = 0; nt < 8; nt++) {
                int col = kv0 + nt * 8 + 2 * (lane & 3);
                if (col >= SEQ_N)     { s[nt][0] = -1e30f; s[nt][2] = -1e30f; }
                if (col + 1 >= SEQ_N) { s[nt][1] = -1e30f; s[nt][3] = -1e30f; }
            }
        }

        // ---- online softmax (rows lane>>2 and lane>>2 + 8) ----
        float mx0 = -1e30f, mx1 = -1e30f;
#pragma unroll
        for (int nt = 0; nt < 8; nt++) {
            mx0 = fmaxf(mx0, fmaxf(s[nt][0], s[nt][1]));
            mx1 = fmaxf(mx1, fmaxf(s[nt][2], s[nt][3]));
        }
        mx0 = fmaxf(mx0, __shfl_xor_sync(0xffffffffu, mx0, 1));
        mx0 = fmaxf(mx0, __shfl_xor_sync(0xffffffffu, mx0, 2));
        mx1 = fmaxf(mx1, __shfl_xor_sync(0xffffffffu, mx1, 1));
        mx1 = fmaxf(mx1, __shfl_xor_sync(0xffffffffu, mx1, 2));
        float mn0 = fmaxf(m0r, mx0), mn1 = fmaxf(m1r, mx1);
        float cr0 = __expf(m0r - mn0), cr1 = __expf(m1r - mn1);
        float sum0 = 0.f, sum1 = 0.f;
#pragma unroll
        for (int nt = 0; nt < 8; nt++) {
            s[nt][0] = __expf(s[nt][0] - mn0);
            s[nt][1] = __expf(s[nt][1] - mn0);
            s[nt][2] = __expf(s[nt][2] - mn1);
            s[nt][3] = __expf(s[nt][3] - mn1);
            sum0 += s[nt][0] + s[nt][1];
            sum1 += s[nt][2] + s[nt][3];
        }
        sum0 += __shfl_xor_sync(0xffffffffu, sum0, 1);
        sum0 += __shfl_xor_sync(0xffffffffu, sum0, 2);
        sum1 += __shfl_xor_sync(0xffffffffu, sum1, 1);
        sum1 += __shfl_xor_sync(0xffffffffu, sum1, 2);
        l0 = l0 * cr0 + sum0;
        l1 = l1 * cr1 + sum1;
        m0r = mn0;
        m1r = mn1;
#pragma unroll
        for (int ne = 0; ne < 8; ne++) {
            of[ne][0] *= cr0; of[ne][1] *= cr0;
            of[ne][2] *= cr1; of[ne][3] *= cr1;
        }

        // ---- P -> warp-private smem (tf32) ----
#pragma unroll
        for (int nt = 0; nt < 8; nt++) {
            int r = lane >> 2;
            int cc = nt * 8 + 2 * (lane & 3);
            Pw[r * 72 + cc]           = f2tf(s[nt][0]);
            Pw[r * 72 + cc + 1]       = f2tf(s[nt][1]);
            Pw[(r + 8) * 72 + cc]     = f2tf(s[nt][2]);
            Pw[(r + 8) * 72 + cc + 1] = f2tf(s[nt][3]);
        }
        __syncwarp();

        // ---- O += P V ----
#pragma unroll
        for (int kc = 0; kc < 8; kc++) {
            uint32_t pa[4];
            pa[0] = Pw[(lane >> 2) * 72 + kc * 8 + (lane & 3)];
            pa[1] = Pw[((lane >> 2) + 8) * 72 + kc * 8 + (lane & 3)];
            pa[2] = Pw[(lane >> 2) * 72 + kc * 8 + (lane & 3) + 4];
            pa[3] = Pw[((lane >> 2) + 8) * 72 + kc * 8 + (lane & 3) + 4];
#pragma unroll
            for (int ne = 0; ne < 8; ne++) {
                uint32_t b[2];
                int e = ne * 8 + (lane >> 2);
                b[0] = Vs[(kc * 8 + (lane & 3)) * 72 + e];
                b[1] = Vs[(kc * 8 + (lane & 3) + 4) * 72 + e];
                mma8(of[ne], pa, b);
            }
        }
        __syncwarp();
    }

    // ---- normalize + write context ----
    float inv0 = 1.f / l0, inv1 = 1.f / l1;
    const int hh = bh % NHEAD;
    const int bb = bh / NHEAD;
    const int qr0 = q0 + w * 16 + (lane >> 2);
    const int qr1 = qr0 + 8;
#pragma unroll
    for (int ne = 0; ne < 8; ne++) {
        int e = hh * 64 + ne * 8 + 2 * (lane & 3);
        if (qr0 < SEQ_N)
            *(float2*)&g_ctx[((size_t)(bb * SEQ_N + qr0)) * DMODEL + e] =
                make_float2(of[ne][0] * inv0, of[ne][1] * inv0);
        if (qr1 < SEQ_N)
            *(float2*)&g_ctx[((size_t)(bb * SEQ_N + qr1)) * DMODEL + e] =
                make_float2(of[ne][2] * inv1, of[ne][3] * inv1);
    }
}

// =================================================================
extern "C" void kernel_launch(void* const* d_in, const int* in_sizes, int n_in,
                              void* d_out, int out_size)
{
    const float* x     = (const float*)d_in[0];
    const float* Wqkv  = (const float*)d_in[1];
    const float* Wproj = (const float*)d_in[2];
    const float* bproj = (const float*)d_in[3];
    const float* freqs = (const float*)d_in[4];
    float* out = (float*)d_out;

    // 1) QKV GEMM (tf32 TC) + fused RoPE
    {
        dim3 grid((M_ROWS + 127) / 128, (3 * DMODEL) / 64);
        gemm_tc<0><<<grid, 256>>>(x, Wqkv, nullptr, nullptr, freqs);
    }
    // 2) attention (tf32 TC)
    {
        cudaFuncSetAttribute(attn_tc,
                             cudaFuncAttributeMaxDynamicSharedMemorySize,
                             ATTN_SMEM_BYTES);
        dim3 grid((SEQ_N + 63) / 64, NUM_B * NHEAD);
        attn_tc<<<grid, 128, ATTN_SMEM_BYTES>>>();
    }
    // 3) proj GEMM (tf32 TC) + bias
    {
        dim3 grid((M_ROWS + 127) / 128, DMODEL / 64);
        gemm_tc<1><<<grid, 256>>>(nullptr, Wproj, out, bproj, nullptr);
    }
}